// round 3
// baseline (speedup 1.0000x reference)
#include <cuda_runtime.h>
#include <cuda_bf16.h>
#include <cstdint>

// DeployPostProcessor: per-batch top-300 of sigmoid(logits[B=256,Q=1000,C=80]).
// Split design: K1 = full-chip streaming prefilter -> global scratch,
//               K2 = per-batch hybrid bitonic sort + emit (+ exact fallback).

#define BATCH       256
#define NPER        80000      // 1000*80 per batch
#define N4          20000      // NPER/4
#define NCLS        80
#define TOPK        300
#define NBUCKET     16384
#define SCHUNK      16         // buckets per thread in fallback scan
#define CAP         1536       // candidate capacity per batch
#define PTHRESH     2.2999f    // count(x>=2.3) ~ 858 +- 29 per 80k N(0,1) draws

#define K1_THREADS  256
#define CHUNKS_PER_B 8
#define F4_PER_CHUNK 2500      // N4 / CHUNKS_PER_B
#define K1_ITERS    10         // ceil(2500/256)

#define K2_THREADS  1024

__device__ unsigned long long g_keys[BATCH * CAP];
__device__ unsigned int       g_cnt[BATCH];

// monotone key for float ordering (ascending float -> ascending uint32)
__device__ __forceinline__ uint32_t fkey(float x) {
    uint32_t b = __float_as_uint(x);
    uint32_t mask = (uint32_t)((int32_t)b >> 31) | 0x80000000u;
    return b ^ mask;
}

__device__ __forceinline__ unsigned long long make_key(float x, uint32_t idx) {
    float s = 1.0f / (1.0f + expf(-x));
    return ((unsigned long long)__float_as_uint(s) << 32)
         | (unsigned long long)(0xFFFFFFFFu - idx);
}

// ================= Kernel 1: streaming prefilter =================
__global__ __launch_bounds__(K1_THREADS)
void prefilter_kernel(const float* __restrict__ logits)
{
    const int blk   = blockIdx.x;
    const int b     = blk >> 3;          // batch
    const int chunk = blk & 7;
    const int lane  = threadIdx.x & 31;
    const uint32_t lt = (1u << lane) - 1u;

    const float4* lg4 = (const float4*)(logits + (size_t)b * NPER)
                        + chunk * F4_PER_CHUNK;
    unsigned long long* kb = g_keys + (size_t)b * CAP;
    const int idx0 = chunk * F4_PER_CHUNK;   // float4 index base within batch

    #pragma unroll
    for (int it = 0; it < K1_ITERS; ++it) {
        int i = it * K1_THREADS + threadIdx.x;
        bool in = i < F4_PER_CHUNK;
        float4 v;
        if (in) v = lg4[i];
        else    v.x = v.y = v.z = v.w = -1e30f;

        bool p0 = v.x >= PTHRESH, p1 = v.y >= PTHRESH;
        bool p2 = v.z >= PTHRESH, p3 = v.w >= PTHRESH;
        uint32_t m0 = __ballot_sync(0xffffffffu, p0);
        uint32_t m1 = __ballot_sync(0xffffffffu, p1);
        uint32_t m2 = __ballot_sync(0xffffffffu, p2);
        uint32_t m3 = __ballot_sync(0xffffffffu, p3);
        uint32_t tot = __popc(m0) + __popc(m1) + __popc(m2) + __popc(m3);
        if (tot == 0) continue;

        uint32_t base = 0;
        if (lane == 0) base = atomicAdd(&g_cnt[b], tot);
        base = __shfl_sync(0xffffffffu, base, 0);

        uint32_t c0 = __popc(m0), c01 = c0 + __popc(m1), c012 = c01 + __popc(m2);
        uint32_t idx4 = (uint32_t)(idx0 + i) * 4u;
        if (p0) { uint32_t p = base + __popc(m0 & lt);        if (p < CAP) kb[p] = make_key(v.x, idx4 + 0); }
        if (p1) { uint32_t p = base + c0  + __popc(m1 & lt);  if (p < CAP) kb[p] = make_key(v.y, idx4 + 1); }
        if (p2) { uint32_t p = base + c01 + __popc(m2 & lt);  if (p < CAP) kb[p] = make_key(v.z, idx4 + 2); }
        if (p3) { uint32_t p = base + c012+ __popc(m3 & lt);  if (p < CAP) kb[p] = make_key(v.w, idx4 + 3); }
    }
}

// ================= Kernel 2: sort + emit (+ fallback) =================
__global__ __launch_bounds__(K2_THREADS, 1)
void sort_emit_kernel(const float* __restrict__ logits,
                      const float* __restrict__ boxes,
                      float* __restrict__ out)
{
    extern __shared__ unsigned char smem_raw[];
    uint32_t* hist = (uint32_t*)smem_raw;                               // 64KB (fallback)
    uint32_t* S    = (uint32_t*)(smem_raw + NBUCKET * 4);               // 4KB
    unsigned long long* keys = (unsigned long long*)(smem_raw + NBUCKET * 4 + K2_THREADS * 4); // 16KB
    uint32_t* scal = (uint32_t*)(smem_raw + NBUCKET * 4 + K2_THREADS * 4 + 2048 * 8);

    const int tid = threadIdx.x;
    const int b   = blockIdx.x;

    uint32_t cnt = g_cnt[b];

    if (cnt >= TOPK && cnt <= CAP) {
        // ---- fast path: load candidates from scratch ----
        const unsigned long long* kb = g_keys + (size_t)b * CAP;
        for (int i = tid; i < (int)cnt; i += K2_THREADS) keys[i] = kb[i];
    } else {
        // ---- fallback: exact histogram select over this batch ----
        const float4* lg4 = (const float4*)(logits + (size_t)b * NPER);
        #pragma unroll
        for (int i = 0; i < SCHUNK; ++i) hist[tid + i * K2_THREADS] = 0;
        if (tid == 0) scal[1] = 0;
        __syncthreads();

        for (int i = tid; i < N4; i += K2_THREADS) {
            float4 v = lg4[i];
            atomicAdd(&hist[fkey(v.x) >> 18], 1u);
            atomicAdd(&hist[fkey(v.y) >> 18], 1u);
            atomicAdd(&hist[fkey(v.z) >> 18], 1u);
            atomicAdd(&hist[fkey(v.w) >> 18], 1u);
        }
        __syncthreads();

        uint32_t csum = 0;
        #pragma unroll
        for (int i = 0; i < SCHUNK; ++i) csum += hist[tid * SCHUNK + i];
        S[tid] = csum;
        __syncthreads();
        for (int off = 1; off < K2_THREADS; off <<= 1) {
            uint32_t v = S[tid] + ((tid + off < K2_THREADS) ? S[tid + off] : 0u);
            __syncthreads();
            S[tid] = v;
            __syncthreads();
        }
        {
            uint32_t basec = (tid == K2_THREADS - 1) ? 0u : S[tid + 1];
            uint32_t mine = S[tid];
            if (basec < TOPK && mine >= TOPK) {
                uint32_t running = basec;
                for (int bk = tid * SCHUNK + SCHUNK - 1; bk >= tid * SCHUNK; --bk) {
                    running += hist[bk];
                    if (running >= TOPK) { scal[0] = (uint32_t)bk; break; }
                }
            }
        }
        __syncthreads();
        uint32_t tbk = scal[0];
        if (tbk > 0) tbk -= 1;               // one-bucket margin for sigmoid ties
        const uint32_t thr_key = tbk << 18;
        __syncthreads();

        for (int i = tid; i < N4; i += K2_THREADS) {
            float4 v = lg4[i];
            float vv[4] = {v.x, v.y, v.z, v.w};
            #pragma unroll
            for (int c = 0; c < 4; ++c) {
                if (fkey(vv[c]) >= thr_key) {
                    uint32_t pos = atomicAdd(&scal[1], 1u);
                    if (pos < 2048) keys[pos] = make_key(vv[c], (uint32_t)(i * 4 + c));
                }
            }
        }
        __syncthreads();
        cnt = scal[1];
        if (cnt > 2048) cnt = 2048;
    }

    if (tid == 0) g_cnt[b] = 0;   // reset for next graph replay (deterministic)

    // ---- pad ----
    int m = (cnt <= 1024) ? 1024 : 2048;
    for (int i = tid; i < m; i += K2_THREADS)
        if ((uint32_t)i >= cnt) keys[i] = 0ull;
    __syncthreads();

    if (m == 1024) {
        // ===== hybrid bitonic sort, 1 element per thread =====
        unsigned long long v = keys[tid];
        // stages k = 2..32 fully in-warp
        #pragma unroll
        for (int k = 2; k <= 32; k <<= 1) {
            #pragma unroll
            for (int j = k >> 1; j; j >>= 1) {
                unsigned long long o = __shfl_xor_sync(0xffffffffu, v, j);
                bool take_max = ((tid & k) == 0) ^ ((tid & j) != 0);
                v = take_max ? (v > o ? v : o) : (v < o ? v : o);
            }
        }
        keys[tid] = v;
        __syncthreads();
        // stages k = 64..1024: smem for j>=32, in-warp bundle for j<32
        #pragma unroll
        for (int k = 64; k <= 1024; k <<= 1) {
            for (int j = k >> 1; j >= 32; j >>= 1) {
                int ixj = tid ^ j;
                if (ixj > tid) {
                    unsigned long long a = keys[tid];
                    unsigned long long c = keys[ixj];
                    bool desc = ((tid & k) == 0);
                    if (desc ? (a < c) : (a > c)) { keys[tid] = c; keys[ixj] = a; }
                }
                __syncthreads();
            }
            v = keys[tid];
            bool desck = ((tid & k) == 0);
            #pragma unroll
            for (int j = 16; j; j >>= 1) {
                unsigned long long o = __shfl_xor_sync(0xffffffffu, v, j);
                bool take_max = desck ^ ((tid & j) != 0);
                v = take_max ? (v > o ? v : o) : (v < o ? v : o);
            }
            keys[tid] = v;
            __syncthreads();
        }
    } else {
        // ===== classic bitonic, m = 2048 (rare) =====
        for (int k = 2; k <= m; k <<= 1) {
            for (int j = k >> 1; j > 0; j >>= 1) {
                for (int i = tid; i < m; i += K2_THREADS) {
                    int ixj = i ^ j;
                    if (ixj > i) {
                        unsigned long long a = keys[i];
                        unsigned long long c = keys[ixj];
                        bool desc = ((i & k) == 0);
                        if (desc ? (a < c) : (a > c)) { keys[i] = c; keys[ixj] = a; }
                    }
                }
                __syncthreads();
            }
        }
    }

    // ---- emit top 300: labels | boxes(xyxy) | scores ----
    if (tid < TOPK) {
        unsigned long long key = keys[tid];
        uint32_t sbits = (uint32_t)(key >> 32);
        uint32_t idx   = 0xFFFFFFFFu - (uint32_t)(key & 0xFFFFFFFFull);
        float score = __uint_as_float(sbits);
        int   label = (int)(idx % NCLS);
        int   q     = (int)(idx / NCLS);

        const float4 bx = ((const float4*)boxes)[b * 1000 + q];
        float cx = bx.x, cy = bx.y, w = bx.z, h = bx.w;

        int base = b * TOPK + tid;
        out[base] = (float)label;                              // labels
        float* bo = out + BATCH * TOPK + (size_t)base * 4;     // boxes
        bo[0] = cx - 0.5f * w;
        bo[1] = cy - 0.5f * h;
        bo[2] = cx + 0.5f * w;
        bo[3] = cy + 0.5f * h;
        out[BATCH * TOPK * 5 + base] = score;                  // scores
    }
}

extern "C" void kernel_launch(void* const* d_in, const int* in_sizes, int n_in,
                              void* d_out, int out_size)
{
    const float* logits = (const float*)d_in[0];
    const float* boxes  = (const float*)d_in[1];
    float* out = (float*)d_out;

    const int smem2 = NBUCKET * 4 + K2_THREADS * 4 + 2048 * 8 + 64;  // 86,080 B
    static bool attr_set = false;
    if (!attr_set) {
        cudaFuncSetAttribute(sort_emit_kernel,
                             cudaFuncAttributeMaxDynamicSharedMemorySize, smem2);
        attr_set = true;
    }

    prefilter_kernel<<<BATCH * CHUNKS_PER_B, K1_THREADS>>>(logits);
    sort_emit_kernel<<<BATCH, K2_THREADS, smem2>>>(logits, boxes, out);
}